// round 14
// baseline (speedup 1.0000x reference)
#include <cuda_runtime.h>
#include <math_constants.h>

#define B_   4
#define C_   84
#define CR_  80          // channels in the max (84 - 4)
#define H_   512
#define W_   512
#define HW_  (H_ * W_)

#define CW   32          // columns per block strip (lane = column)
#define TH   16          // output rows per block
#define NQ   4           // warp q owns probs-channels [q*20,q*20+20), store-channels [q*21,q*21+21)
#define CPQ  21          // store/reload channels per warp (covers 0..83)
#define PPQ  20          // probs channels per warp (covers 0..79)
#define NT   128
#define RING 4

// ---------------------------------------------------------------------------
// Fused NMS, sparse-store variant. Block = 32-col x 16-row strip of one batch.
// Per output row h (ONE barrier):
//   probs_row(h+1): warp q streams its 20 max-channels (scalar, coalesced),
//     running max -> pbq ring slot (h+1)&3; warps 0/1 compute the two
//     halo-column 80-ch maxes (shuffle) -> ph ring. Pad rows -> 0.
//   __syncthreads();
//   mask row h from ring slots (h-1,h,h+1)&3 (reference: strict > for row
//     above + left, >= for right + row below; zero padding).
//   Survivor lanes (~1/9) re-read their 21 channels (L1/L2-hot: same lines
//     the probs pass touched one row ago) and store; others store 0.0f.
// Ring-skew safety (R13 argument): iter h writes slot (h+1)&3 pre-barrier,
// reads (h-1..h+1)&3 post-barrier; a fast warp's next write (h+2)&3 is
// disjoint, and its (h+3)&3 write sits behind the next barrier. One barrier
// per row suffices with RING=4.
// ---------------------------------------------------------------------------
__global__ void __launch_bounds__(NT, 8) fused_nms_sparse(
    const float* __restrict__ points, float* __restrict__ out)
{
    __shared__ float pbq[RING][NQ][CW];   // per-quarter partial row maxes
    __shared__ float ph[RING][2];         // halo-column combined maxes (L/R)

    const int tid = threadIdx.x;
    const int q   = tid >> 5;             // warp = channel quarter
    const int col = tid & 31;             // lane = column in strip
    const int x0  = blockIdx.x * CW;
    const int h0  = blockIdx.y * TH;
    const int b   = blockIdx.z;
    const size_t bbase = (size_t)b * C_ * HW_;

    const float* inb  = points + bbase + x0 + col;
    float*       outb = out    + bbase + x0 + col;

    // halo column for warps 0/1: warp0 -> x0-1, warp1 -> x0+CW
    const int hx = (q == 0) ? (x0 - 1) : (x0 + CW);
    const bool halo_in = (q < 2) && (hx >= 0) && (hx < W_);
    const float* hbase = points + bbase + hx;

    // ---- probs for row g -> ring (all rows identical: 20 ch per warp) ----
    auto probs_row = [&](int g) {
        const int s = g & (RING - 1);
        float m = 0.0f;                   // pad value
        if (g >= 0 && g < H_) {
            const float* rp = inb + (size_t)g * W_;
            m = -CUDART_INF_F;
            #pragma unroll
            for (int i = 0; i < PPQ; i++)           // q*20+i < 80 always
                m = fmaxf(m, __ldg(rp + (size_t)(q * PPQ + i) * HW_));
        }
        pbq[s][q][col] = m;

        if (q < 2) {
            float hm = 0.0f;
            if (halo_in && g >= 0 && g < H_) {
                const float* hp = hbase + (size_t)g * W_;
                hm = -CUDART_INF_F;
                #pragma unroll
                for (int k = 0; k < 3; k++) {
                    int c = col + k * 32;
                    if (c < CR_) hm = fmaxf(hm, __ldg(hp + (size_t)c * HW_));
                }
                #pragma unroll
                for (int off = 16; off; off >>= 1)
                    hm = fmaxf(hm, __shfl_xor_sync(0xffffffffu, hm, off));
            }
            if (col == 0) ph[s][q] = hm;
        }
    };

    // combined probs at (ring slot s, strip col c), c in [-1, CW]
    auto P = [&](int s, int c) -> float {
        if (c < 0)   return ph[s][0];
        if (c >= CW) return ph[s][1];
        return fmaxf(fmaxf(pbq[s][0][c], pbq[s][1][c]),
                     fmaxf(pbq[s][2][c], pbq[s][3][c]));
    };

    // ---- prologue ---------------------------------------------------------
    probs_row(h0 - 1);
    probs_row(h0);

    // ---- main pipeline: one barrier per row -------------------------------
    for (int h = h0; h < h0 + TH; h++) {
        probs_row(h + 1);
        __syncthreads();

        const int s0 = (h - 1) & (RING - 1);
        const int s1 = h       & (RING - 1);
        const int s2 = (h + 1) & (RING - 1);
        const float p = P(s1, col);
        const bool mok =
            (p >  P(s0, col - 1)) &&   // (-1,-1)
            (p >  P(s0, col    )) &&   // (-1, 0)
            (p >  P(s0, col + 1)) &&   // (-1,+1)
            (p >  P(s1, col - 1)) &&   // ( 0,-1) left
            (p >= P(s1, col + 1)) &&   // ( 0,+1) right
            (p >= P(s2, col - 1)) &&   // (+1,-1)
            (p >= P(s2, col    )) &&   // (+1, 0)
            (p >= P(s2, col + 1));     // (+1,+1)

        const float* ip = inb  + (size_t)h * W_;
        float*       op = outb + (size_t)h * W_;
        if (mok) {
            // survivor (~1/9): copy 21 channels; lines are L1/L2-hot from the
            // probs pass one row-iteration ago (ch 80-83 miss -> small DRAM).
            #pragma unroll
            for (int i = 0; i < CPQ; i++) {
                const size_t o = (size_t)(q * CPQ + i) * HW_;
                __stcs(op + o, __ldg(ip + o));
            }
        } else {
            // suppressed: exact zero, no loads at all
            #pragma unroll
            for (int i = 0; i < CPQ; i++)
                __stcs(op + (size_t)(q * CPQ + i) * HW_, 0.0f);
        }
    }
}

// ---------------------------------------------------------------------------
extern "C" void kernel_launch(void* const* d_in, const int* in_sizes, int n_in,
                              void* d_out, int out_size)
{
    const float* points = (const float*)d_in[0];
    float* out = (float*)d_out;

    dim3 grid(W_ / CW, H_ / TH, B_);   // (16, 32, 4) = 2048 blocks
    fused_nms_sparse<<<grid, NT>>>(points, out);
}

// round 15
// speedup vs baseline: 1.1080x; 1.1080x over previous
#include <cuda_runtime.h>
#include <math_constants.h>

#define B_   4
#define C_   84
#define CR_  80          // channels in the max (84 - 4)
#define H_   512
#define W_   512
#define HW_  (H_ * W_)

#define CW   32          // columns per block strip (one warp-lane per column)
#define TH   16          // output rows per block
#define NQ   4           // channel-quarter split: warp q owns channels [q*21, q*21+21)
#define CPQ  21          // full-row channels per warp
#define PPQ  20          // probs-only-row channels per warp
#define NT   128         // NQ warps * 32 lanes
#define RING 4           // probs ring depth (enables 1 barrier per row)

// ---------------------------------------------------------------------------
// Fused NMS, row-pipelined, register-resident values (R13 structure) at
// TH=16 so the grid (2048 blocks) fills 8 blocks/SM (R14's occupancy win,
// without R14's failed sparse reload).
//
// Block owns a 32-col x 16-row strip of one batch. Warp q owns channel
// quarter q; lane = column. Per output row h (ONE barrier):
//   load row h+1: 21 channels -> regs w[], running 80-ch partial max ->
//     pbq ring slot (h+1)&3; warps 0/1 also compute the two halo-column
//     80-ch maxes (shuffle-reduce) -> ph ring.
//   __syncthreads();
//   mask row h from ring slots (h-1,h,h+1)&3, combining the 4 quarter maxes
//     inline. Reference semantics (window idx, center=4): strict > for the
//     row above + left neighbor, >= for right + row below; zero padding.
//   multiply v[] (row h regs) by mask, streaming stores; v = w.
//
// Ring safety: iter h writes slot (h+1)&3 pre-barrier and reads (h-1..h+1)&3
// post-barrier; a fast warp's next write (h+2)&3 is disjoint and its
// (h+3)&3 write sits behind the next barrier. One barrier per row suffices.
// Input lines are read exactly once (+2 probs-only halo rows per strip,
// +2 halo columns that ride L2 off neighbor strips).
// ---------------------------------------------------------------------------
__global__ void __launch_bounds__(NT, 8) fused_nms_reg16(
    const float* __restrict__ points, float* __restrict__ out)
{
    __shared__ float pbq[RING][NQ][CW];   // per-quarter partial row maxes
    __shared__ float ph[RING][2];         // halo-column combined maxes (L/R)

    const int tid  = threadIdx.x;
    const int q    = tid >> 5;            // warp = channel quarter
    const int col  = tid & 31;            // lane = column in strip
    const int x0   = blockIdx.x * CW;
    const int h0   = blockIdx.y * TH;
    const int b    = blockIdx.z;
    const size_t bbase = (size_t)b * C_ * HW_;

    const float* inb  = points + bbase + x0 + col;
    float*       outb = out    + bbase + x0 + col;

    // halo column for warps 0/1: warp0 -> x0-1, warp1 -> x0+CW
    const int hx = (q == 0) ? (x0 - 1) : (x0 + CW);
    const bool halo_in = (q < 2) && (hx >= 0) && (hx < W_);
    const float* hbase = points + bbase + hx;

    // ---- probs bookkeeping for a loaded/pad row -------------------------
    auto probs_row = [&](int g, float m) {
        const int s = g & (RING - 1);
        pbq[s][q][col] = m;
        if (q < 2) {
            float hm = 0.0f;
            if (halo_in && g >= 0 && g < H_) {
                const float* hp = hbase + (size_t)g * W_;
                hm = -CUDART_INF_F;
                #pragma unroll
                for (int k = 0; k < 3; k++) {
                    int c = col + k * 32;
                    if (c < CR_) hm = fmaxf(hm, __ldg(hp + (size_t)c * HW_));
                }
                #pragma unroll
                for (int off = 16; off; off >>= 1)
                    hm = fmaxf(hm, __shfl_xor_sync(0xffffffffu, hm, off));
            }
            if (col == 0) ph[s][q] = hm;
        }
    };

    // ---- probs-only row (halo rows / pad rows) --------------------------
    auto probs_only_row = [&](int g) {
        float m = 0.0f;                   // pad value
        if (g >= 0 && g < H_) {
            const float* rp = inb + (size_t)g * W_;
            m = -CUDART_INF_F;
            #pragma unroll
            for (int i = 0; i < PPQ; i++)  // q*20+i < 80 always
                m = fmaxf(m, __ldg(rp + (size_t)(q * PPQ + i) * HW_));
        }
        probs_row(g, m);
    };

    // combined probs at (ring slot s, strip col c), c in [-1, CW]
    auto P = [&](int s, int c) -> float {
        if (c < 0)   return ph[s][0];
        if (c >= CW) return ph[s][1];
        return fmaxf(fmaxf(pbq[s][0][c], pbq[s][1][c]),
                     fmaxf(pbq[s][2][c], pbq[s][3][c]));
    };

    float v[CPQ], w[CPQ];

    // ---- prologue: probs(h0-1), full(h0) -> v ---------------------------
    probs_only_row(h0 - 1);
    {
        const float* rp = inb + (size_t)h0 * W_;
        float m = -CUDART_INF_F;
        #pragma unroll
        for (int i = 0; i < CPQ; i++) {
            int c = q * CPQ + i;
            float val = __ldg(rp + (size_t)c * HW_);
            v[i] = val;
            if (c < CR_) m = fmaxf(m, val);
        }
        probs_row(h0, m);
    }

    // ---- main pipeline: one barrier per row -----------------------------
    for (int h = h0; h < h0 + TH; h++) {
        const int gn = h + 1;
        if (gn < h0 + TH) {
            const float* rp = inb + (size_t)gn * W_;
            float m = -CUDART_INF_F;
            #pragma unroll
            for (int i = 0; i < CPQ; i++) {
                int c = q * CPQ + i;
                float val = __ldg(rp + (size_t)c * HW_);
                w[i] = val;
                if (c < CR_) m = fmaxf(m, val);
            }
            probs_row(gn, m);
        } else {
            probs_only_row(gn);           // row h0+TH (or pad if == H)
        }
        __syncthreads();

        // mask + multiply row h
        {
            const int s0 = (h - 1) & (RING - 1);
            const int s1 = h       & (RING - 1);
            const int s2 = (h + 1) & (RING - 1);
            const float p = P(s1, col);
            bool mok =
                (p >  P(s0, col - 1)) &&   // (-1,-1)
                (p >  P(s0, col    )) &&   // (-1, 0)
                (p >  P(s0, col + 1)) &&   // (-1,+1)
                (p >  P(s1, col - 1)) &&   // ( 0,-1) left
                (p >= P(s1, col + 1)) &&   // ( 0,+1) right
                (p >= P(s2, col - 1)) &&   // (+1,-1)
                (p >= P(s2, col    )) &&   // (+1, 0)
                (p >= P(s2, col + 1));     // (+1,+1)
            const float msk = mok ? 1.0f : 0.0f;

            float* op = outb + (size_t)h * W_;
            #pragma unroll
            for (int i = 0; i < CPQ; i++)
                __stcs(op + (size_t)(q * CPQ + i) * HW_, v[i] * msk);
        }

        if (gn < h0 + TH) {
            #pragma unroll
            for (int i = 0; i < CPQ; i++) v[i] = w[i];
        }
        // no second barrier: next iteration writes ring slot (h+2)&3,
        // disjoint from the three slots read above; max warp skew = 1 iter.
    }
}

// ---------------------------------------------------------------------------
extern "C" void kernel_launch(void* const* d_in, const int* in_sizes, int n_in,
                              void* d_out, int out_size)
{
    const float* points = (const float*)d_in[0];
    float* out = (float*)d_out;

    dim3 grid(W_ / CW, H_ / TH, B_);   // (16, 32, 4) = 2048 blocks -> 8/SM
    fused_nms_reg16<<<grid, NT>>>(points, out);
}